// round 14
// baseline (speedup 1.0000x reference)
#include <cuda_runtime.h>
#include <float.h>
#include <math.h>

// Problem constants
#define BATCH 2
#define NPT   64      // user inputs per batch
#define CCH   256     // feature channels
#define KCLS  10      // classes
#define KT    32      // K-tile per pipeline stage

// Separable Gaussian tables: g_ex[lvl][b][px][64n] (inv folded), g_ey[lvl][b][py][64n]
__device__ __forceinline__ int etab_off(int level, int b) {
    return level == 0 ? b * 4096 : (level == 1 ? 8192 + b * 2048 : 12288 + b * 1024);
}
__device__ __forceinline__ int part_off(int level) {
    return level == 0 ? 0 : (level == 1 ? 1048576 : 1572864);
}

// Scratch (device globals; no allocation allowed)
__device__ float g_ex[14336];
__device__ float g_ey[14336];
__device__ float g_part[1835008];                     // K-split partial templates
__device__ float g_tmplT[3 * BATCH * CCH * NPT];      // template [lvl][b][c][n]
__device__ float g_pcor[2 * BATCH * NPT * 5376];      // c-split partial correlations
__device__ int   g_order[BATCH * NPT];                // n indices grouped by class
__device__ int   g_start[BATCH * 12];                 // group boundaries per batch

// int64-vs-int32 detection: labels in [1,10]; if int64 LE, word 1 == high(label0) == 0.
__device__ __forceinline__ bool detect64(const int* labels_i32) {
    return labels_i32[1] == 0;
}
__device__ __forceinline__ int geti(const int* p, int i, bool is64) {
    return p[is64 ? 2 * i : i];
}

// cp.async helpers
__device__ __forceinline__ void cp_async16(void* smem_dst, const void* gsrc) {
    unsigned s = (unsigned)__cvta_generic_to_shared(smem_dst);
    asm volatile("cp.async.cg.shared.global [%0], [%1], 16;\n" :: "r"(s), "l"(gsrc));
}
__device__ __forceinline__ void cp_commit() {
    asm volatile("cp.async.commit_group;\n" ::: "memory");
}
__device__ __forceinline__ void cp_wait1() {
    asm volatile("cp.async.wait_group 1;\n" ::: "memory");
}
__device__ __forceinline__ void cp_wait0() {
    asm volatile("cp.async.wait_group 0;\n" ::: "memory");
}

// ---------------------------------------------------------------------------
// K0: separable Gaussian tables + PARALLEL label grouping (2 blocks).
// grid 384 = 3 lvl x 2 b x 64 n, 64 thr.
// ---------------------------------------------------------------------------
__global__ void k_heat(const float* __restrict__ centers,
                       const int* __restrict__ idx_i32,
                       const int* __restrict__ labels_i32) {
    __shared__ float redx[64], redy[64];
    __shared__ int slab[64];

    int blk = blockIdx.x;
    int level = blk >> 7;
    int rem = blk & 127;
    int b = rem >> 6, n = rem & 63;

    int hd = 64 >> level;
    int scale = 8 << level;
    int t = threadIdx.x;

    bool is64 = detect64(labels_i32);

    // label grouping, parallel across 64 threads, in the 2 level-2 n==0 blocks
    if (level == 2 && n == 0) {
        slab[t] = geti(labels_i32, b * NPT + t, is64);
        __syncthreads();
        int myl = slab[t];
        int rank = 0, base = 0;
        for (int m = 0; m < NPT; m++) {
            int lm = slab[m];
            rank += (m < t && lm == myl) ? 1 : 0;
            base += (lm < myl) ? 1 : 0;
        }
        g_order[b * NPT + base + rank] = t;
        if (t <= KCLS) {
            int st = 0;
            for (int m = 0; m < NPT; m++)
                st += (slab[m] < t + 1) ? 1 : 0;
            g_start[b * 12 + t] = st;   // start[k] = #{labels < k+1}; start[10]=64
        }
        __syncthreads();
    }

    bool valid = geti(idx_i32, b * NPT + n, is64) != -1;
    float cx = centers[(b * NPT + n) * 2 + 0];
    float cy = centers[(b * NPT + n) * 2 + 1];
    const float alpha = -0.5f / 9.0f;  // sigma = 3

    float exv = 0.f, eyv = 0.f;
    if (t < hd) {
        float coord = t * (float)scale + 0.5f;
        float dx = coord - cx, dy = coord - cy;
        exv = __expf(alpha * dx * dx);
        eyv = __expf(alpha * dy * dy);
    }
    redx[t] = exv; redy[t] = eyv;
    __syncthreads();
    for (int s = 32; s > 0; s >>= 1) {
        if (t < s) { redx[t] += redx[t + s]; redy[t] += redy[t + s]; }
        __syncthreads();
    }
    float inv = 1.0f / (redx[0] * redy[0] + 1e-8f);

    int off = etab_off(level, b);
    if (t < hd) {
        g_ex[off + t * 64 + n] = valid ? exv * inv : 0.f;
        g_ey[off + t * 64 + n] = eyv;
    }
}

// ---------------------------------------------------------------------------
// K1a: template GEMM partials, pipelined. T[n][c] = sum_p heat[n][p]*feat[c][p]
// sA computed on the fly from ex/ey tables; sB (feat) transpose-staged.
// grid 448: lvl0 256 (4ct x 32ks x 2b, kchunk=128), lvl1 128 (16ks, 64),
//           lvl2 64 (8ks, 32). 256 thr, 4x4 per thread.
// ---------------------------------------------------------------------------
__global__ void __launch_bounds__(256) k_tmpl_part(
                            const float* __restrict__ x0,
                            const float* __restrict__ x1,
                            const float* __restrict__ x2) {
    __shared__ float sA[2][KT][68];   // [buf][k][n]
    __shared__ float sB[2][KT][68];   // [buf][k][c_local]

    int blk = blockIdx.x;
    int level, lb;
    if (blk < 256)      { level = 0; lb = blk; }
    else if (blk < 384) { level = 1; lb = blk - 256; }
    else                { level = 2; lb = blk - 384; }

    int ct, ks, b, kchunk, HW;
    if (level == 0)      { ct = lb & 3; ks = (lb >> 2) & 31; b = lb >> 7; kchunk = 128; HW = 4096; }
    else if (level == 1) { ct = lb & 3; ks = (lb >> 2) & 15; b = lb >> 6; kchunk = 64;  HW = 1024; }
    else                 { ct = lb & 3; ks = (lb >> 2) & 7;  b = lb >> 5; kchunk = 32;  HW = 256;  }
    int S = kchunk / KT;              // stages: 4 / 2 / 1
    int p0 = ks * kchunk;
    int hdm = (64 >> level) - 1;      // px mask
    int hdsh = 6 - level;             // py shift

    const float* feat = (level == 0) ? x0 : (level == 1) ? x1 : x2;
    const float* exb = g_ex + etab_off(level, b);
    const float* eyb = g_ey + etab_off(level, b);

    int tid = threadIdx.x;
    int ty = tid >> 4, tx = tid & 15;

    // sA compute-staging: 512 f4 per stage, 2 per thread
    int ar0 = tid >> 4, anq = (tid & 15) * 4;
    int ar1 = ar0 + 16;

    // sB transpose staging: thread -> (c_row, kseg)
    int crow = tid >> 2;              // 0..63
    int kseg = (tid & 3) * 8;
    const float* fb = feat + (size_t)(b * CCH + ct * 64 + crow) * HW + p0 + kseg;

    float4 rb0, rb1, rex0, rey0, rex1, rey1;

#define LOAD_STAGE_REGS(pbase)                                            \
    {                                                                     \
        int pA0 = (pbase) + ar0, pA1 = (pbase) + ar1;                     \
        rex0 = *(const float4*)&exb[(pA0 & hdm) * 64 + anq];              \
        rey0 = *(const float4*)&eyb[(pA0 >> hdsh) * 64 + anq];            \
        rex1 = *(const float4*)&exb[(pA1 & hdm) * 64 + anq];              \
        rey1 = *(const float4*)&eyb[(pA1 >> hdsh) * 64 + anq];            \
    }
#define STORE_STAGE(bufi)                                                 \
    {                                                                     \
        *(float4*)&sA[bufi][ar0][anq] = make_float4(                      \
            rex0.x * rey0.x, rex0.y * rey0.y, rex0.z * rey0.z, rex0.w * rey0.w); \
        *(float4*)&sA[bufi][ar1][anq] = make_float4(                      \
            rex1.x * rey1.x, rex1.y * rey1.y, rex1.z * rey1.z, rex1.w * rey1.w); \
        _Pragma("unroll")                                                 \
        for (int i = 0; i < 4; i++) {                                     \
            sB[bufi][kseg + i][crow] = ((const float*)&rb0)[i];           \
            sB[bufi][kseg + 4 + i][crow] = ((const float*)&rb1)[i];       \
        }                                                                 \
    }

    // prologue: stage 0
    LOAD_STAGE_REGS(p0);
    rb0 = *(const float4*)(fb + 0);
    rb1 = *(const float4*)(fb + 4);
    STORE_STAGE(0);
    __syncthreads();

    float acc[4][4];
#pragma unroll
    for (int i = 0; i < 4; i++)
#pragma unroll
        for (int j = 0; j < 4; j++) acc[i][j] = 0.f;

    int n0 = ty * 4, c0 = tx * 4;

    for (int kt = 0; kt < S; kt++) {
        int buf = kt & 1, nb = buf ^ 1;
        if (kt < S - 1) {
            LOAD_STAGE_REGS(p0 + (kt + 1) * KT);
            rb0 = *(const float4*)(fb + (kt + 1) * KT + 0);
            rb1 = *(const float4*)(fb + (kt + 1) * KT + 4);
        }

#pragma unroll
        for (int k = 0; k < KT; k++) {
            float4 a = *(const float4*)&sA[buf][k][n0];
            float4 bb = *(const float4*)&sB[buf][k][c0];
            acc[0][0] += a.x * bb.x; acc[0][1] += a.x * bb.y;
            acc[0][2] += a.x * bb.z; acc[0][3] += a.x * bb.w;
            acc[1][0] += a.y * bb.x; acc[1][1] += a.y * bb.y;
            acc[1][2] += a.y * bb.z; acc[1][3] += a.y * bb.w;
            acc[2][0] += a.z * bb.x; acc[2][1] += a.z * bb.y;
            acc[2][2] += a.z * bb.z; acc[2][3] += a.z * bb.w;
            acc[3][0] += a.w * bb.x; acc[3][1] += a.w * bb.y;
            acc[3][2] += a.w * bb.z; acc[3][3] += a.w * bb.w;
        }

        if (kt < S - 1) {
            STORE_STAGE(nb);
            __syncthreads();
        }
    }
#undef LOAD_STAGE_REGS
#undef STORE_STAGE

    // write 4x4 partial
    float* pp = g_part + part_off(level) + (size_t)((ks * BATCH + b) * NPT) * CCH + ct * 64;
#pragma unroll
    for (int i = 0; i < 4; i++) {
        float4 v = make_float4(acc[i][0], acc[i][1], acc[i][2], acc[i][3]);
        *(float4*)&pp[(size_t)(n0 + i) * CCH + c0] = v;
    }
}

// ---------------------------------------------------------------------------
// K1b: reduce partials over ks, write transposed template [lvl][b][c][n]
// ---------------------------------------------------------------------------
__global__ void k_tmpl_reduce() {
    int blk = blockIdx.x;
    int level = blk / 128;
    int rem = blk - level * 128;
    int b = rem >> 6, n = rem & 63;
    int KS = (level == 0) ? 32 : (level == 1) ? 16 : 8;
    int c = threadIdx.x;

    const float* pbase = g_part + part_off(level);
    float s = 0.f;
    for (int ks = 0; ks < KS; ks++)
        s += pbase[(size_t)((ks * BATCH + b) * NPT + n) * CCH + c];

    g_tmplT[level * (BATCH * CCH * NPT) + (b * CCH + c) * NPT + n] = s;
}

// ---------------------------------------------------------------------------
// K2: correlation as cp.async GEMM, c-split by 2 (R10 2-stage version).
// Block 128 thr (4 warps), tile 32n(half) x 64px, K=128 (split) in 4 stages.
// Per k: 2 LDS.128 + 1 LDS.64 + 16 FFMA (84% density). Partial cor -> g_pcor.
// half==0 blocks copy their split's 128 feat channels from staged sB.
// grid 672: lvl0 512 (64 tiles x 2half x 2b x 2split), lvl1 128, lvl2 32.
// ---------------------------------------------------------------------------
__global__ void __launch_bounds__(128) k_cor(
                      const float* __restrict__ x0,
                      const float* __restrict__ x1,
                      const float* __restrict__ x2,
                      float* __restrict__ out) {
    __shared__ float sA[2][KT][32];   // [buf][k=c][n_local]
    __shared__ float sB[2][KT][64];   // [buf][k=c][px]

    int blk = blockIdx.x;
    int level, lb;
    if (blk < 512)      { level = 0; lb = blk; }
    else if (blk < 640) { level = 1; lb = blk - 512; }
    else                { level = 2; lb = blk - 640; }

    int split = lb & 1;
    int b = (lb >> 1) & 1;
    int half = (lb >> 2) & 1;
    int tile = lb >> 3;
    int HW = 4096 >> (2 * level);
    int px0 = tile * 64;
    int oOff = (level == 0) ? 0 : (level == 1) ? 2179072 : 2723840;
    int q5376 = (level == 0) ? 0 : (level == 1) ? 4096 : 5120;
    const float* feat = (level == 0) ? x0 : (level == 1) ? x1 : x2;

    int tid = threadIdx.x;
    int lane = tid & 31;
    int w = tid >> 5;

    const float* tsrc = g_tmplT + level * (BATCH * CCH * NPT) + (size_t)b * CCH * NPT
                        + (size_t)(split * 128) * NPT + half * 32;
    const float* fbase = feat + (size_t)(b * CCH + split * 128) * HW + px0;
    float* obase = out + oOff + (size_t)(b * (CCH + KCLS) + split * 128) * HW + px0;

    // sA: 256 f4/stage (2/thread); sB: 512 f4/stage (4/thread)
#define STAGE_CP(bufi, c0base)                                                    \
    {                                                                             \
        _Pragma("unroll")                                                         \
        for (int j = 0; j < 2; j++) {                                             \
            int idx = tid + j * 128;                                              \
            int r = idx >> 3, cq = (idx & 7) * 4;                                 \
            cp_async16(&sA[bufi][r][cq], tsrc + (size_t)((c0base) + r) * NPT + cq);\
        }                                                                         \
        _Pragma("unroll")                                                         \
        for (int j = 0; j < 4; j++) {                                             \
            int idx = tid + j * 128;                                              \
            int r = idx >> 4, cc = (idx & 15) * 4;                                \
            cp_async16(&sB[bufi][r][cc], fbase + (size_t)((c0base) + r) * HW + cc);\
        }                                                                         \
        cp_commit();                                                              \
    }

    STAGE_CP(0, 0);

    float accA[8], accB[8];
#pragma unroll
    for (int i = 0; i < 8; i++) { accA[i] = 0.f; accB[i] = 0.f; }

    int nw0 = w * 8;

    for (int kt = 0; kt < 128 / KT; kt++) {
        int buf = kt & 1;
        if (kt < 128 / KT - 1) {
            STAGE_CP(buf ^ 1, (kt + 1) * KT);
            cp_wait1();
        } else {
            cp_wait0();
        }
        __syncthreads();

#pragma unroll
        for (int k = 0; k < KT; k++) {
            float2 bv = *(const float2*)&sB[buf][k][lane * 2];
            float4 a0 = *(const float4*)&sA[buf][k][nw0];
            float4 a1 = *(const float4*)&sA[buf][k][nw0 + 4];
            accA[0] += a0.x * bv.x;  accB[0] += a0.x * bv.y;
            accA[1] += a0.y * bv.x;  accB[1] += a0.y * bv.y;
            accA[2] += a0.z * bv.x;  accB[2] += a0.z * bv.y;
            accA[3] += a0.w * bv.x;  accB[3] += a0.w * bv.y;
            accA[4] += a1.x * bv.x;  accB[4] += a1.x * bv.y;
            accA[5] += a1.y * bv.x;  accB[5] += a1.y * bv.y;
            accA[6] += a1.z * bv.x;  accB[6] += a1.z * bv.y;
            accA[7] += a1.w * bv.x;  accB[7] += a1.w * bv.y;
        }

        if (half == 0) {
            int c0 = kt * KT;
#pragma unroll
            for (int j = 0; j < 4; j++) {
                int idx = tid + j * 128;
                int r = idx >> 4, cc = (idx & 15) * 4;
                float4 v = *(const float4*)&sB[buf][r][cc];
                *(float4*)&obase[(size_t)(c0 + r) * HW + cc] = v;
            }
        }
        __syncthreads();
    }
#undef STAGE_CP

    // write partial correlations: g_pcor[(split*B+b)][n][q]
    float* pc = g_pcor + ((size_t)(split * BATCH + b) * NPT) * 5376
                + q5376 + px0 + lane * 2;
#pragma unroll
    for (int j = 0; j < 8; j++) {
        int n = half * 32 + nw0 + j;
        *(float2*)&pc[(size_t)n * 5376] = make_float2(accA[j], accB[j]);
    }
}

// ---------------------------------------------------------------------------
// K3: dense-load split-sum into SMEM, then per-class max from SMEM.
// Block = (b, 32-q chunk): 256 thr load 64n x 32q sums (16 unrolled LDGs each,
// coalesced), then compute 10 class maxes per q from SMEM. grid 336.
// ---------------------------------------------------------------------------
__global__ void __launch_bounds__(256) k_fin(float* __restrict__ out) {
    __shared__ float sv[64][33];      // [n][q_local]
    __shared__ int s_order[NPT];
    __shared__ int s_start[11];

    int blk = blockIdx.x;
    int b = blk >= 168;
    int chunk = blk - b * 168;
    int q0 = chunk * 32;
    int tid = threadIdx.x;

    if (tid < NPT) s_order[tid] = g_order[b * NPT + tid];
    if (tid < 11) s_start[tid] = g_start[b * 12 + tid];

    const float* pc0 = g_pcor + ((size_t)(0 * BATCH + b) * NPT) * 5376 + q0;
    const float* pc1 = g_pcor + ((size_t)(1 * BATCH + b) * NPT) * 5376 + q0;

#pragma unroll
    for (int j = 0; j < 8; j++) {
        int i = tid + j * 256;
        int n = i >> 5, ql = i & 31;
        sv[n][ql] = pc0[(size_t)n * 5376 + ql] + pc1[(size_t)n * 5376 + ql];
    }
    __syncthreads();

    for (int o = tid; o < KCLS * 32; o += 256) {
        int k = o >> 5, ql = o & 31;
        int q = q0 + ql;

        int i0 = s_start[k], i1 = s_start[k + 1];
        float m = -FLT_MAX;
        for (int i = i0; i < i1; i++)
            m = fmaxf(m, sv[s_order[i]][ql]);
        if (i0 == i1) m = 0.f;

        int HW, hw, oOff;
        if (q < 4096)      { HW = 4096; hw = q;        oOff = 0; }
        else if (q < 5120) { HW = 1024; hw = q - 4096; oOff = 2179072; }
        else               { HW = 256;  hw = q - 5120; oOff = 2723840; }

        out[oOff + (size_t)(b * (CCH + KCLS) + CCH + k) * HW + hw] = m;
    }
}

// ---------------------------------------------------------------------------
extern "C" void kernel_launch(void* const* d_in, const int* in_sizes, int n_in,
                              void* d_out, int out_size) {
    (void)in_sizes; (void)n_in; (void)out_size;
    const float* x0      = (const float*)d_in[0];
    const float* x1      = (const float*)d_in[1];
    const float* x2      = (const float*)d_in[2];
    const float* centers = (const float*)d_in[3];
    const int*   idx     = (const int*)d_in[4];
    const int*   labels  = (const int*)d_in[5];
    float* out = (float*)d_out;

    k_heat<<<384, 64>>>(centers, idx, labels);
    k_tmpl_part<<<448, 256>>>(x0, x1, x2);
    k_tmpl_reduce<<<384, 256>>>();
    k_cor<<<672, 128>>>(x0, x1, x2, out);
    k_fin<<<336, 256>>>(out);
}

// round 15
// speedup vs baseline: 1.3328x; 1.3328x over previous
#include <cuda_runtime.h>
#include <float.h>
#include <math.h>

// Problem constants
#define BATCH 2
#define NPT   64      // user inputs per batch
#define CCH   256     // feature channels
#define KCLS  10      // classes
#define KT    32      // K-tile per pipeline stage

// Separable Gaussian tables: g_ex[lvl][b][px][64n] (inv folded), g_ey[lvl][b][py][64n]
__device__ __forceinline__ int etab_off(int level, int b) {
    return level == 0 ? b * 4096 : (level == 1 ? 8192 + b * 2048 : 12288 + b * 1024);
}
__device__ __forceinline__ int part_off(int level) {
    return level == 0 ? 0 : (level == 1 ? 1048576 : 1572864);
}

// Scratch (device globals; no allocation allowed)
__device__ float g_ex[14336];
__device__ float g_ey[14336];
__device__ float g_part[1835008];                     // K-split partial templates
__device__ float g_tmplT[3 * BATCH * CCH * NPT];      // template [lvl][b][c][n]
__device__ float g_pcor[2 * BATCH * NPT * 5376];      // c-split partial correlations
__device__ int   g_order[BATCH * NPT];                // n indices grouped by class
__device__ int   g_start[BATCH * 12];                 // group boundaries per batch

// int64-vs-int32 detection: labels in [1,10]; if int64 LE, word 1 == high(label0) == 0.
__device__ __forceinline__ bool detect64(const int* labels_i32) {
    return labels_i32[1] == 0;
}
__device__ __forceinline__ int geti(const int* p, int i, bool is64) {
    return p[is64 ? 2 * i : i];
}

// cp.async helpers
__device__ __forceinline__ void cp_async16(void* smem_dst, const void* gsrc) {
    unsigned s = (unsigned)__cvta_generic_to_shared(smem_dst);
    asm volatile("cp.async.cg.shared.global [%0], [%1], 16;\n" :: "r"(s), "l"(gsrc));
}
__device__ __forceinline__ void cp_commit() {
    asm volatile("cp.async.commit_group;\n" ::: "memory");
}
__device__ __forceinline__ void cp_wait1() {
    asm volatile("cp.async.wait_group 1;\n" ::: "memory");
}
__device__ __forceinline__ void cp_wait0() {
    asm volatile("cp.async.wait_group 0;\n" ::: "memory");
}

// ---------------------------------------------------------------------------
// K0: separable Gaussian tables + PARALLEL label grouping (2 blocks).
// grid 384 = 3 lvl x 2 b x 64 n, 64 thr.
// ---------------------------------------------------------------------------
__global__ void k_heat(const float* __restrict__ centers,
                       const int* __restrict__ idx_i32,
                       const int* __restrict__ labels_i32) {
    __shared__ float redx[64], redy[64];
    __shared__ int slab[64];

    int blk = blockIdx.x;
    int level = blk >> 7;
    int rem = blk & 127;
    int b = rem >> 6, n = rem & 63;

    int hd = 64 >> level;
    int scale = 8 << level;
    int t = threadIdx.x;

    bool is64 = detect64(labels_i32);

    // label grouping, parallel across 64 threads, in the 2 level-2 n==0 blocks
    if (level == 2 && n == 0) {
        slab[t] = geti(labels_i32, b * NPT + t, is64);
        __syncthreads();
        int myl = slab[t];
        int rank = 0, base = 0;
        for (int m = 0; m < NPT; m++) {
            int lm = slab[m];
            rank += (m < t && lm == myl) ? 1 : 0;
            base += (lm < myl) ? 1 : 0;
        }
        g_order[b * NPT + base + rank] = t;
        if (t <= KCLS) {
            int st = 0;
            for (int m = 0; m < NPT; m++)
                st += (slab[m] < t + 1) ? 1 : 0;
            g_start[b * 12 + t] = st;   // start[k] = #{labels < k+1}; start[10]=64
        }
        __syncthreads();
    }

    bool valid = geti(idx_i32, b * NPT + n, is64) != -1;
    float cx = centers[(b * NPT + n) * 2 + 0];
    float cy = centers[(b * NPT + n) * 2 + 1];
    const float alpha = -0.5f / 9.0f;  // sigma = 3

    float exv = 0.f, eyv = 0.f;
    if (t < hd) {
        float coord = t * (float)scale + 0.5f;
        float dx = coord - cx, dy = coord - cy;
        exv = __expf(alpha * dx * dx);
        eyv = __expf(alpha * dy * dy);
    }
    redx[t] = exv; redy[t] = eyv;
    __syncthreads();
    for (int s = 32; s > 0; s >>= 1) {
        if (t < s) { redx[t] += redx[t + s]; redy[t] += redy[t + s]; }
        __syncthreads();
    }
    float inv = 1.0f / (redx[0] * redy[0] + 1e-8f);

    int off = etab_off(level, b);
    if (t < hd) {
        g_ex[off + t * 64 + n] = valid ? exv * inv : 0.f;
        g_ey[off + t * 64 + n] = eyv;
    }
}

// ---------------------------------------------------------------------------
// K1a: template GEMM partials, pipelined. T[n][c] = sum_p heat[n][p]*feat[c][p]
// sA computed on the fly from ex/ey tables; sB (feat) transpose-staged.
// grid 448: lvl0 256 (4ct x 32ks x 2b, kchunk=128), lvl1 128 (16ks, 64),
//           lvl2 64 (8ks, 32). 256 thr, 4x4 per thread.
// ---------------------------------------------------------------------------
__global__ void __launch_bounds__(256) k_tmpl_part(
                            const float* __restrict__ x0,
                            const float* __restrict__ x1,
                            const float* __restrict__ x2) {
    __shared__ float sA[2][KT][68];   // [buf][k][n]
    __shared__ float sB[2][KT][68];   // [buf][k][c_local]

    int blk = blockIdx.x;
    int level, lb;
    if (blk < 256)      { level = 0; lb = blk; }
    else if (blk < 384) { level = 1; lb = blk - 256; }
    else                { level = 2; lb = blk - 384; }

    int ct, ks, b, kchunk, HW;
    if (level == 0)      { ct = lb & 3; ks = (lb >> 2) & 31; b = lb >> 7; kchunk = 128; HW = 4096; }
    else if (level == 1) { ct = lb & 3; ks = (lb >> 2) & 15; b = lb >> 6; kchunk = 64;  HW = 1024; }
    else                 { ct = lb & 3; ks = (lb >> 2) & 7;  b = lb >> 5; kchunk = 32;  HW = 256;  }
    int S = kchunk / KT;              // stages: 4 / 2 / 1
    int p0 = ks * kchunk;
    int hdm = (64 >> level) - 1;      // px mask
    int hdsh = 6 - level;             // py shift

    const float* feat = (level == 0) ? x0 : (level == 1) ? x1 : x2;
    const float* exb = g_ex + etab_off(level, b);
    const float* eyb = g_ey + etab_off(level, b);

    int tid = threadIdx.x;
    int ty = tid >> 4, tx = tid & 15;

    // sA compute-staging: 512 f4 per stage, 2 per thread
    int ar0 = tid >> 4, anq = (tid & 15) * 4;
    int ar1 = ar0 + 16;

    // sB transpose staging: thread -> (c_row, kseg)
    int crow = tid >> 2;              // 0..63
    int kseg = (tid & 3) * 8;
    const float* fb = feat + (size_t)(b * CCH + ct * 64 + crow) * HW + p0 + kseg;

    float4 rb0, rb1, rex0, rey0, rex1, rey1;

#define LOAD_STAGE_REGS(pbase)                                            \
    {                                                                     \
        int pA0 = (pbase) + ar0, pA1 = (pbase) + ar1;                     \
        rex0 = *(const float4*)&exb[(pA0 & hdm) * 64 + anq];              \
        rey0 = *(const float4*)&eyb[(pA0 >> hdsh) * 64 + anq];            \
        rex1 = *(const float4*)&exb[(pA1 & hdm) * 64 + anq];              \
        rey1 = *(const float4*)&eyb[(pA1 >> hdsh) * 64 + anq];            \
    }
#define STORE_STAGE(bufi)                                                 \
    {                                                                     \
        *(float4*)&sA[bufi][ar0][anq] = make_float4(                      \
            rex0.x * rey0.x, rex0.y * rey0.y, rex0.z * rey0.z, rex0.w * rey0.w); \
        *(float4*)&sA[bufi][ar1][anq] = make_float4(                      \
            rex1.x * rey1.x, rex1.y * rey1.y, rex1.z * rey1.z, rex1.w * rey1.w); \
        _Pragma("unroll")                                                 \
        for (int i = 0; i < 4; i++) {                                     \
            sB[bufi][kseg + i][crow] = ((const float*)&rb0)[i];           \
            sB[bufi][kseg + 4 + i][crow] = ((const float*)&rb1)[i];       \
        }                                                                 \
    }

    // prologue: stage 0
    LOAD_STAGE_REGS(p0);
    rb0 = *(const float4*)(fb + 0);
    rb1 = *(const float4*)(fb + 4);
    STORE_STAGE(0);
    __syncthreads();

    float acc[4][4];
#pragma unroll
    for (int i = 0; i < 4; i++)
#pragma unroll
        for (int j = 0; j < 4; j++) acc[i][j] = 0.f;

    int n0 = ty * 4, c0 = tx * 4;

    for (int kt = 0; kt < S; kt++) {
        int buf = kt & 1, nb = buf ^ 1;
        if (kt < S - 1) {
            LOAD_STAGE_REGS(p0 + (kt + 1) * KT);
            rb0 = *(const float4*)(fb + (kt + 1) * KT + 0);
            rb1 = *(const float4*)(fb + (kt + 1) * KT + 4);
        }

#pragma unroll
        for (int k = 0; k < KT; k++) {
            float4 a = *(const float4*)&sA[buf][k][n0];
            float4 bb = *(const float4*)&sB[buf][k][c0];
            acc[0][0] += a.x * bb.x; acc[0][1] += a.x * bb.y;
            acc[0][2] += a.x * bb.z; acc[0][3] += a.x * bb.w;
            acc[1][0] += a.y * bb.x; acc[1][1] += a.y * bb.y;
            acc[1][2] += a.y * bb.z; acc[1][3] += a.y * bb.w;
            acc[2][0] += a.z * bb.x; acc[2][1] += a.z * bb.y;
            acc[2][2] += a.z * bb.z; acc[2][3] += a.z * bb.w;
            acc[3][0] += a.w * bb.x; acc[3][1] += a.w * bb.y;
            acc[3][2] += a.w * bb.z; acc[3][3] += a.w * bb.w;
        }

        if (kt < S - 1) {
            STORE_STAGE(nb);
            __syncthreads();
        }
    }
#undef LOAD_STAGE_REGS
#undef STORE_STAGE

    // write 4x4 partial
    float* pp = g_part + part_off(level) + (size_t)((ks * BATCH + b) * NPT) * CCH + ct * 64;
#pragma unroll
    for (int i = 0; i < 4; i++) {
        float4 v = make_float4(acc[i][0], acc[i][1], acc[i][2], acc[i][3]);
        *(float4*)&pp[(size_t)(n0 + i) * CCH + c0] = v;
    }
}

// ---------------------------------------------------------------------------
// K1b: reduce partials over ks, write transposed template [lvl][b][c][n]
// ---------------------------------------------------------------------------
__global__ void k_tmpl_reduce() {
    int blk = blockIdx.x;
    int level = blk / 128;
    int rem = blk - level * 128;
    int b = rem >> 6, n = rem & 63;
    int KS = (level == 0) ? 32 : (level == 1) ? 16 : 8;
    int c = threadIdx.x;

    const float* pbase = g_part + part_off(level);
    float s = 0.f;
    for (int ks = 0; ks < KS; ks++)
        s += pbase[(size_t)((ks * BATCH + b) * NPT + n) * CCH + c];

    g_tmplT[level * (BATCH * CCH * NPT) + (b * CCH + c) * NPT + n] = s;
}

// ---------------------------------------------------------------------------
// K2: correlation as cp.async GEMM, c-split by 2 (2-stage pipeline).
// Block 128 thr (4 warps), tile 32n(half) x 64px, K=128 (split) in 4 stages.
// Per k: 2 LDS.128 + 1 LDS.64 + 16 FFMA (84% density). Partial cor -> g_pcor.
// half==0 blocks copy their split's 128 feat channels from staged sB.
// grid 672: lvl0 512 (64 tiles x 2half x 2b x 2split), lvl1 128, lvl2 32.
// ---------------------------------------------------------------------------
__global__ void __launch_bounds__(128) k_cor(
                      const float* __restrict__ x0,
                      const float* __restrict__ x1,
                      const float* __restrict__ x2,
                      float* __restrict__ out) {
    __shared__ float sA[2][KT][32];   // [buf][k=c][n_local]
    __shared__ float sB[2][KT][64];   // [buf][k=c][px]

    int blk = blockIdx.x;
    int level, lb;
    if (blk < 512)      { level = 0; lb = blk; }
    else if (blk < 640) { level = 1; lb = blk - 512; }
    else                { level = 2; lb = blk - 640; }

    int split = lb & 1;
    int b = (lb >> 1) & 1;
    int half = (lb >> 2) & 1;
    int tile = lb >> 3;
    int HW = 4096 >> (2 * level);
    int px0 = tile * 64;
    int oOff = (level == 0) ? 0 : (level == 1) ? 2179072 : 2723840;
    int q5376 = (level == 0) ? 0 : (level == 1) ? 4096 : 5120;
    const float* feat = (level == 0) ? x0 : (level == 1) ? x1 : x2;

    int tid = threadIdx.x;
    int lane = tid & 31;
    int w = tid >> 5;

    const float* tsrc = g_tmplT + level * (BATCH * CCH * NPT) + (size_t)b * CCH * NPT
                        + (size_t)(split * 128) * NPT + half * 32;
    const float* fbase = feat + (size_t)(b * CCH + split * 128) * HW + px0;
    float* obase = out + oOff + (size_t)(b * (CCH + KCLS) + split * 128) * HW + px0;

    // sA: 256 f4/stage (2/thread); sB: 512 f4/stage (4/thread)
#define STAGE_CP(bufi, c0base)                                                    \
    {                                                                             \
        _Pragma("unroll")                                                         \
        for (int j = 0; j < 2; j++) {                                             \
            int idx = tid + j * 128;                                              \
            int r = idx >> 3, cq = (idx & 7) * 4;                                 \
            cp_async16(&sA[bufi][r][cq], tsrc + (size_t)((c0base) + r) * NPT + cq);\
        }                                                                         \
        _Pragma("unroll")                                                         \
        for (int j = 0; j < 4; j++) {                                             \
            int idx = tid + j * 128;                                              \
            int r = idx >> 4, cc = (idx & 15) * 4;                                \
            cp_async16(&sB[bufi][r][cc], fbase + (size_t)((c0base) + r) * HW + cc);\
        }                                                                         \
        cp_commit();                                                              \
    }

    STAGE_CP(0, 0);

    float accA[8], accB[8];
#pragma unroll
    for (int i = 0; i < 8; i++) { accA[i] = 0.f; accB[i] = 0.f; }

    int nw0 = w * 8;

    for (int kt = 0; kt < 128 / KT; kt++) {
        int buf = kt & 1;
        if (kt < 128 / KT - 1) {
            STAGE_CP(buf ^ 1, (kt + 1) * KT);
            cp_wait1();
        } else {
            cp_wait0();
        }
        __syncthreads();

#pragma unroll
        for (int k = 0; k < KT; k++) {
            float2 bv = *(const float2*)&sB[buf][k][lane * 2];
            float4 a0 = *(const float4*)&sA[buf][k][nw0];
            float4 a1 = *(const float4*)&sA[buf][k][nw0 + 4];
            accA[0] += a0.x * bv.x;  accB[0] += a0.x * bv.y;
            accA[1] += a0.y * bv.x;  accB[1] += a0.y * bv.y;
            accA[2] += a0.z * bv.x;  accB[2] += a0.z * bv.y;
            accA[3] += a0.w * bv.x;  accB[3] += a0.w * bv.y;
            accA[4] += a1.x * bv.x;  accB[4] += a1.x * bv.y;
            accA[5] += a1.y * bv.x;  accB[5] += a1.y * bv.y;
            accA[6] += a1.z * bv.x;  accB[6] += a1.z * bv.y;
            accA[7] += a1.w * bv.x;  accB[7] += a1.w * bv.y;
        }

        if (half == 0) {
            int c0 = kt * KT;
#pragma unroll
            for (int j = 0; j < 4; j++) {
                int idx = tid + j * 128;
                int r = idx >> 4, cc = (idx & 15) * 4;
                float4 v = *(const float4*)&sB[buf][r][cc];
                *(float4*)&obase[(size_t)(c0 + r) * HW + cc] = v;
            }
        }
        __syncthreads();
    }
#undef STAGE_CP

    // write partial correlations: g_pcor[(split*B+b)][n][q]
    float* pc = g_pcor + ((size_t)(split * BATCH + b) * NPT) * 5376
                + q5376 + px0 + lane * 2;
#pragma unroll
    for (int j = 0; j < 8; j++) {
        int n = half * 32 + nw0 + j;
        *(float2*)&pc[(size_t)n * 5376] = make_float2(accA[j], accB[j]);
    }
}

// ---------------------------------------------------------------------------
// K3: sum c-split partials + per-class max, one thread per (b,k,q) output
// (R13 proven structure) with 4x-unrolled group loop for MLP.
// ---------------------------------------------------------------------------
__global__ void __launch_bounds__(256) k_fin(float* __restrict__ out) {
    __shared__ int s_order[BATCH * NPT];
    __shared__ int s_start[BATCH * 12];

    int tid = threadIdx.x;
    if (tid < BATCH * NPT) s_order[tid] = g_order[tid];
    if (tid < BATCH * 12) s_start[tid] = g_start[tid];
    __syncthreads();

    int t = blockIdx.x * 256 + tid;
    if (t >= BATCH * KCLS * 5376) return;
    int q = t % 5376;
    int rest = t / 5376;
    int k = rest % KCLS;
    int b = rest / KCLS;

    const float* pc0 = g_pcor + ((size_t)(0 * BATCH + b) * NPT) * 5376 + q;
    const float* pc1 = g_pcor + ((size_t)(1 * BATCH + b) * NPT) * 5376 + q;
    const int* so = s_order + b * NPT;

    int i0 = s_start[b * 12 + k], i1 = s_start[b * 12 + k + 1];
    float m = -FLT_MAX;
    int i = i0;
    for (; i + 4 <= i1; i += 4) {
        int n0 = so[i], n1 = so[i + 1], n2 = so[i + 2], n3 = so[i + 3];
        float a0 = pc0[(size_t)n0 * 5376], b0 = pc1[(size_t)n0 * 5376];
        float a1 = pc0[(size_t)n1 * 5376], b1 = pc1[(size_t)n1 * 5376];
        float a2 = pc0[(size_t)n2 * 5376], b2 = pc1[(size_t)n2 * 5376];
        float a3 = pc0[(size_t)n3 * 5376], b3 = pc1[(size_t)n3 * 5376];
        float v0 = a0 + b0, v1 = a1 + b1, v2 = a2 + b2, v3 = a3 + b3;
        m = fmaxf(m, fmaxf(fmaxf(v0, v1), fmaxf(v2, v3)));
    }
    for (; i < i1; i++) {
        int n = so[i];
        m = fmaxf(m, pc0[(size_t)n * 5376] + pc1[(size_t)n * 5376]);
    }
    if (i0 == i1) m = 0.f;

    int HW, hw, oOff;
    if (q < 4096)      { HW = 4096; hw = q;        oOff = 0; }
    else if (q < 5120) { HW = 1024; hw = q - 4096; oOff = 2179072; }
    else               { HW = 256;  hw = q - 5120; oOff = 2723840; }

    out[oOff + (size_t)(b * (CCH + KCLS) + CCH + k) * HW + hw] = m;
}

// ---------------------------------------------------------------------------
extern "C" void kernel_launch(void* const* d_in, const int* in_sizes, int n_in,
                              void* d_out, int out_size) {
    (void)in_sizes; (void)n_in; (void)out_size;
    const float* x0      = (const float*)d_in[0];
    const float* x1      = (const float*)d_in[1];
    const float* x2      = (const float*)d_in[2];
    const float* centers = (const float*)d_in[3];
    const int*   idx     = (const int*)d_in[4];
    const int*   labels  = (const int*)d_in[5];
    float* out = (float*)d_out;

    k_heat<<<384, 64>>>(centers, idx, labels);
    k_tmpl_part<<<448, 256>>>(x0, x1, x2);
    k_tmpl_reduce<<<384, 256>>>();
    k_cor<<<672, 128>>>(x0, x1, x2, out);
    k_fin<<<420, 256>>>(out);
}

// round 16
// speedup vs baseline: 1.4185x; 1.0643x over previous
#include <cuda_runtime.h>
#include <float.h>
#include <math.h>

// Problem constants
#define BATCH 2
#define NPT   64      // user inputs per batch
#define CCH   256     // feature channels
#define KCLS  10      // classes
#define KT    32      // K-tile per pipeline stage

__device__ __forceinline__ int part_off(int level) {
    return level == 0 ? 0 : (level == 1 ? 1048576 : 1572864);
}

// Scratch (device globals; no allocation allowed)
__device__ float g_part[1835008];                     // K-split partial templates
__device__ float g_tmplT[3 * BATCH * CCH * NPT];      // template [lvl][b][c][n]
__device__ float g_pcor[2 * BATCH * NPT * 5376];      // c-split partial correlations
__device__ int   g_order[BATCH * NPT];                // n indices grouped by class
__device__ int   g_start[BATCH * 12];                 // group boundaries per batch

// int64-vs-int32 detection: labels in [1,10]; if int64 LE, word 1 == high(label0) == 0.
__device__ __forceinline__ bool detect64(const int* labels_i32) {
    return labels_i32[1] == 0;
}
__device__ __forceinline__ int geti(const int* p, int i, bool is64) {
    return p[is64 ? 2 * i : i];
}

// cp.async helpers
__device__ __forceinline__ void cp_async16(void* smem_dst, const void* gsrc) {
    unsigned s = (unsigned)__cvta_generic_to_shared(smem_dst);
    asm volatile("cp.async.cg.shared.global [%0], [%1], 16;\n" :: "r"(s), "l"(gsrc));
}
__device__ __forceinline__ void cp_commit() {
    asm volatile("cp.async.commit_group;\n" ::: "memory");
}
__device__ __forceinline__ void cp_wait1() {
    asm volatile("cp.async.wait_group 1;\n" ::: "memory");
}
__device__ __forceinline__ void cp_wait0() {
    asm volatile("cp.async.wait_group 0;\n" ::: "memory");
}

// ---------------------------------------------------------------------------
// K1a: template GEMM partials, pipelined, with INLINE Gaussian generation.
// T[n][c] = sum_p heat[n][p]*feat[c][p]. sA computed on the fly via __expf
// (separable Gaussian; per-n scale = valid/(Sx*Sy+1e-8) from a block prologue);
// sB (feat) transpose-staged via LDG+STS.
// grid 448: lvl0 256 (4ct x 32ks x 2b, kchunk=128), lvl1 128 (16ks, 64),
//           lvl2 64 (8ks, 32). 256 thr, 4x4 per thread.
// ---------------------------------------------------------------------------
__global__ void __launch_bounds__(256) k_tmpl_part(
                            const float* __restrict__ x0,
                            const float* __restrict__ x1,
                            const float* __restrict__ x2,
                            const float* __restrict__ centers,
                            const int* __restrict__ idx_i32,
                            const int* __restrict__ labels_i32) {
    __shared__ float sA[2][KT][68];   // [buf][k][n]
    __shared__ float sB[2][KT][68];   // [buf][k][c_local]
    __shared__ float sCx[64], sCy[64], sScale[64];
    __shared__ float sRed[2][256];

    int blk = blockIdx.x;
    int level, lb;
    if (blk < 256)      { level = 0; lb = blk; }
    else if (blk < 384) { level = 1; lb = blk - 256; }
    else                { level = 2; lb = blk - 384; }

    int ct, ks, b, kchunk, HW;
    if (level == 0)      { ct = lb & 3; ks = (lb >> 2) & 31; b = lb >> 7; kchunk = 128; HW = 4096; }
    else if (level == 1) { ct = lb & 3; ks = (lb >> 2) & 15; b = lb >> 6; kchunk = 64;  HW = 1024; }
    else                 { ct = lb & 3; ks = (lb >> 2) & 7;  b = lb >> 5; kchunk = 32;  HW = 256;  }
    int S = kchunk / KT;              // stages: 4 / 2 / 1
    int p0 = ks * kchunk;
    int hd = 64 >> level;
    int hdm = hd - 1;                 // px mask
    int hdsh = 6 - level;             // py shift
    const float scalef = (float)(8 << level);
    const float alpha = -0.5f / 9.0f; // sigma = 3

    const float* feat = (level == 0) ? x0 : (level == 1) ? x1 : x2;

    int tid = threadIdx.x;
    int ty = tid >> 4, tx = tid & 15;

    // ---- prologue: centers + per-n normalization scale (valid/(Sx*Sy+1e-8)) ----
    {
        bool is64 = detect64(labels_i32);
        int nn = tid & 63, quarter = tid >> 6;
        float2 ctr = *(const float2*)&centers[(b * NPT + nn) * 2];
        if (quarter == 0) { sCx[nn] = ctr.x; sCy[nn] = ctr.y; }
        float sx = 0.f, sy = 0.f;
        int cnt = hd >> 2;
        for (int i = 0; i < cnt; i++) {
            int p = quarter * cnt + i;
            float coord = p * scalef + 0.5f;
            float dx = coord - ctr.x, dy = coord - ctr.y;
            sx += __expf(alpha * dx * dx);
            sy += __expf(alpha * dy * dy);
        }
        sRed[0][quarter * 64 + nn] = sx;
        sRed[1][quarter * 64 + nn] = sy;
        __syncthreads();
        if (tid < 64) {
            float Sx = sRed[0][tid] + sRed[0][64 + tid] + sRed[0][128 + tid] + sRed[0][192 + tid];
            float Sy = sRed[1][tid] + sRed[1][64 + tid] + sRed[1][128 + tid] + sRed[1][192 + tid];
            bool valid = geti(idx_i32, b * NPT + tid, is64) != -1;
            sScale[tid] = valid ? 1.0f / (Sx * Sy + 1e-8f) : 0.f;
        }
        __syncthreads();
    }

    // sA compute-staging: 2 rows x 4 n per thread
    int ar0 = tid >> 4, anq = (tid & 15) * 4;
    int ar1 = ar0 + 16;

    // sB transpose staging: thread -> (c_row, kseg)
    int crow = tid >> 2;              // 0..63
    int kseg = (tid & 3) * 8;
    const float* fb = feat + (size_t)(b * CCH + ct * 64 + crow) * HW + p0 + kseg;

    float4 rb0, rb1;
    float va0[4], va1[4];

#define COMPUTE_STAGE_REGS(pbase)                                          \
    {                                                                      \
        int pA0 = (pbase) + ar0, pA1 = (pbase) + ar1;                      \
        float x0c = (pA0 & hdm) * scalef + 0.5f;                           \
        float y0c = (pA0 >> hdsh) * scalef + 0.5f;                         \
        float x1c = (pA1 & hdm) * scalef + 0.5f;                           \
        float y1c = (pA1 >> hdsh) * scalef + 0.5f;                         \
        _Pragma("unroll")                                                  \
        for (int j = 0; j < 4; j++) {                                      \
            float cx = sCx[anq + j], cy = sCy[anq + j], sc = sScale[anq + j]; \
            float dx0 = x0c - cx, dy0 = y0c - cy;                          \
            float dx1 = x1c - cx, dy1 = y1c - cy;                          \
            va0[j] = (sc * __expf(alpha * dx0 * dx0)) * __expf(alpha * dy0 * dy0); \
            va1[j] = (sc * __expf(alpha * dx1 * dx1)) * __expf(alpha * dy1 * dy1); \
        }                                                                  \
    }
#define STORE_STAGE(bufi)                                                 \
    {                                                                     \
        *(float4*)&sA[bufi][ar0][anq] = make_float4(va0[0], va0[1], va0[2], va0[3]); \
        *(float4*)&sA[bufi][ar1][anq] = make_float4(va1[0], va1[1], va1[2], va1[3]); \
        _Pragma("unroll")                                                 \
        for (int i = 0; i < 4; i++) {                                     \
            sB[bufi][kseg + i][crow] = ((const float*)&rb0)[i];           \
            sB[bufi][kseg + 4 + i][crow] = ((const float*)&rb1)[i];       \
        }                                                                 \
    }

    // prologue: stage 0
    COMPUTE_STAGE_REGS(p0);
    rb0 = *(const float4*)(fb + 0);
    rb1 = *(const float4*)(fb + 4);
    STORE_STAGE(0);
    __syncthreads();

    float acc[4][4];
#pragma unroll
    for (int i = 0; i < 4; i++)
#pragma unroll
        for (int j = 0; j < 4; j++) acc[i][j] = 0.f;

    int n0 = ty * 4, c0 = tx * 4;

    for (int kt = 0; kt < S; kt++) {
        int buf = kt & 1, nb = buf ^ 1;
        if (kt < S - 1) {
            COMPUTE_STAGE_REGS(p0 + (kt + 1) * KT);
            rb0 = *(const float4*)(fb + (kt + 1) * KT + 0);
            rb1 = *(const float4*)(fb + (kt + 1) * KT + 4);
        }

#pragma unroll
        for (int k = 0; k < KT; k++) {
            float4 a = *(const float4*)&sA[buf][k][n0];
            float4 bb = *(const float4*)&sB[buf][k][c0];
            acc[0][0] += a.x * bb.x; acc[0][1] += a.x * bb.y;
            acc[0][2] += a.x * bb.z; acc[0][3] += a.x * bb.w;
            acc[1][0] += a.y * bb.x; acc[1][1] += a.y * bb.y;
            acc[1][2] += a.y * bb.z; acc[1][3] += a.y * bb.w;
            acc[2][0] += a.z * bb.x; acc[2][1] += a.z * bb.y;
            acc[2][2] += a.z * bb.z; acc[2][3] += a.z * bb.w;
            acc[3][0] += a.w * bb.x; acc[3][1] += a.w * bb.y;
            acc[3][2] += a.w * bb.z; acc[3][3] += a.w * bb.w;
        }

        if (kt < S - 1) {
            STORE_STAGE(nb);
            __syncthreads();
        }
    }
#undef COMPUTE_STAGE_REGS
#undef STORE_STAGE

    // write 4x4 partial
    float* pp = g_part + part_off(level) + (size_t)((ks * BATCH + b) * NPT) * CCH + ct * 64;
#pragma unroll
    for (int i = 0; i < 4; i++) {
        float4 v = make_float4(acc[i][0], acc[i][1], acc[i][2], acc[i][3]);
        *(float4*)&pp[(size_t)(n0 + i) * CCH + c0] = v;
    }
}

// ---------------------------------------------------------------------------
// K1b: reduce partials over ks, write transposed template [lvl][b][c][n].
// Blocks 0 and 1 additionally compute the label grouping (parallel).
// ---------------------------------------------------------------------------
__global__ void k_tmpl_reduce(const int* __restrict__ labels_i32) {
    __shared__ int slab[64];

    if (blockIdx.x < 2) {
        int bb = blockIdx.x;
        bool is64 = detect64(labels_i32);
        int t = threadIdx.x;
        if (t < 64) slab[t] = geti(labels_i32, bb * NPT + t, is64);
        __syncthreads();
        if (t < 64) {
            int myl = slab[t];
            int rank = 0, base = 0;
            for (int m = 0; m < NPT; m++) {
                int lm = slab[m];
                rank += (m < t && lm == myl) ? 1 : 0;
                base += (lm < myl) ? 1 : 0;
            }
            g_order[bb * NPT + base + rank] = t;
            if (t <= KCLS) {
                int st = 0;
                for (int m = 0; m < NPT; m++)
                    st += (slab[m] < t + 1) ? 1 : 0;
                g_start[bb * 12 + t] = st;   // start[k] = #{labels < k+1}; start[10]=64
            }
        }
    }

    int blk = blockIdx.x;
    int level = blk / 128;
    int rem = blk - level * 128;
    int b = rem >> 6, n = rem & 63;
    int KS = (level == 0) ? 32 : (level == 1) ? 16 : 8;
    int c = threadIdx.x;

    const float* pbase = g_part + part_off(level);
    float s = 0.f;
    for (int ks = 0; ks < KS; ks++)
        s += pbase[(size_t)((ks * BATCH + b) * NPT + n) * CCH + c];

    g_tmplT[level * (BATCH * CCH * NPT) + (b * CCH + c) * NPT + n] = s;
}

// ---------------------------------------------------------------------------
// K2: correlation as cp.async GEMM, c-split by 2 (2-stage pipeline).
// Block 128 thr (4 warps), tile 32n(half) x 64px, K=128 (split) in 4 stages.
// Per k: 2 LDS.128 + 1 LDS.64 + 16 FFMA (84% density). Partial cor -> g_pcor.
// half==0 blocks copy their split's 128 feat channels from staged sB.
// grid 672: lvl0 512 (64 tiles x 2half x 2b x 2split), lvl1 128, lvl2 32.
// ---------------------------------------------------------------------------
__global__ void __launch_bounds__(128) k_cor(
                      const float* __restrict__ x0,
                      const float* __restrict__ x1,
                      const float* __restrict__ x2,
                      float* __restrict__ out) {
    __shared__ float sA[2][KT][32];   // [buf][k=c][n_local]
    __shared__ float sB[2][KT][64];   // [buf][k=c][px]

    int blk = blockIdx.x;
    int level, lb;
    if (blk < 512)      { level = 0; lb = blk; }
    else if (blk < 640) { level = 1; lb = blk - 512; }
    else                { level = 2; lb = blk - 640; }

    int split = lb & 1;
    int b = (lb >> 1) & 1;
    int half = (lb >> 2) & 1;
    int tile = lb >> 3;
    int HW = 4096 >> (2 * level);
    int px0 = tile * 64;
    int oOff = (level == 0) ? 0 : (level == 1) ? 2179072 : 2723840;
    int q5376 = (level == 0) ? 0 : (level == 1) ? 4096 : 5120;
    const float* feat = (level == 0) ? x0 : (level == 1) ? x1 : x2;

    int tid = threadIdx.x;
    int lane = tid & 31;
    int w = tid >> 5;

    const float* tsrc = g_tmplT + level * (BATCH * CCH * NPT) + (size_t)b * CCH * NPT
                        + (size_t)(split * 128) * NPT + half * 32;
    const float* fbase = feat + (size_t)(b * CCH + split * 128) * HW + px0;
    float* obase = out + oOff + (size_t)(b * (CCH + KCLS) + split * 128) * HW + px0;

    // sA: 256 f4/stage (2/thread); sB: 512 f4/stage (4/thread)
#define STAGE_CP(bufi, c0base)                                                    \
    {                                                                             \
        _Pragma("unroll")                                                         \
        for (int j = 0; j < 2; j++) {                                             \
            int idx = tid + j * 128;                                              \
            int r = idx >> 3, cq = (idx & 7) * 4;                                 \
            cp_async16(&sA[bufi][r][cq], tsrc + (size_t)((c0base) + r) * NPT + cq);\
        }                                                                         \
        _Pragma("unroll")                                                         \
        for (int j = 0; j < 4; j++) {                                             \
            int idx = tid + j * 128;                                              \
            int r = idx >> 4, cc = (idx & 15) * 4;                                \
            cp_async16(&sB[bufi][r][cc], fbase + (size_t)((c0base) + r) * HW + cc);\
        }                                                                         \
        cp_commit();                                                              \
    }

    STAGE_CP(0, 0);

    float accA[8], accB[8];
#pragma unroll
    for (int i = 0; i < 8; i++) { accA[i] = 0.f; accB[i] = 0.f; }

    int nw0 = w * 8;

    for (int kt = 0; kt < 128 / KT; kt++) {
        int buf = kt & 1;
        if (kt < 128 / KT - 1) {
            STAGE_CP(buf ^ 1, (kt + 1) * KT);
            cp_wait1();
        } else {
            cp_wait0();
        }
        __syncthreads();

#pragma unroll
        for (int k = 0; k < KT; k++) {
            float2 bv = *(const float2*)&sB[buf][k][lane * 2];
            float4 a0 = *(const float4*)&sA[buf][k][nw0];
            float4 a1 = *(const float4*)&sA[buf][k][nw0 + 4];
            accA[0] += a0.x * bv.x;  accB[0] += a0.x * bv.y;
            accA[1] += a0.y * bv.x;  accB[1] += a0.y * bv.y;
            accA[2] += a0.z * bv.x;  accB[2] += a0.z * bv.y;
            accA[3] += a0.w * bv.x;  accB[3] += a0.w * bv.y;
            accA[4] += a1.x * bv.x;  accB[4] += a1.x * bv.y;
            accA[5] += a1.y * bv.x;  accB[5] += a1.y * bv.y;
            accA[6] += a1.z * bv.x;  accB[6] += a1.z * bv.y;
            accA[7] += a1.w * bv.x;  accB[7] += a1.w * bv.y;
        }

        if (half == 0) {
            int c0 = kt * KT;
#pragma unroll
            for (int j = 0; j < 4; j++) {
                int idx = tid + j * 128;
                int r = idx >> 4, cc = (idx & 15) * 4;
                float4 v = *(const float4*)&sB[buf][r][cc];
                *(float4*)&obase[(size_t)(c0 + r) * HW + cc] = v;
            }
        }
        __syncthreads();
    }
#undef STAGE_CP

    // write partial correlations: g_pcor[(split*B+b)][n][q]
    float* pc = g_pcor + ((size_t)(split * BATCH + b) * NPT) * 5376
                + q5376 + px0 + lane * 2;
#pragma unroll
    for (int j = 0; j < 8; j++) {
        int n = half * 32 + nw0 + j;
        *(float2*)&pc[(size_t)n * 5376] = make_float2(accA[j], accB[j]);
    }
}

// ---------------------------------------------------------------------------
// K3: sum c-split partials + per-class max, one thread per (b,k,q) output,
// 4x-unrolled group loop for MLP.
// ---------------------------------------------------------------------------
__global__ void __launch_bounds__(256) k_fin(float* __restrict__ out) {
    __shared__ int s_order[BATCH * NPT];
    __shared__ int s_start[BATCH * 12];

    int tid = threadIdx.x;
    if (tid < BATCH * NPT) s_order[tid] = g_order[tid];
    if (tid < BATCH * 12) s_start[tid] = g_start[tid];
    __syncthreads();

    int t = blockIdx.x * 256 + tid;
    if (t >= BATCH * KCLS * 5376) return;
    int q = t % 5376;
    int rest = t / 5376;
    int k = rest % KCLS;
    int b = rest / KCLS;

    const float* pc0 = g_pcor + ((size_t)(0 * BATCH + b) * NPT) * 5376 + q;
    const float* pc1 = g_pcor + ((size_t)(1 * BATCH + b) * NPT) * 5376 + q;
    const int* so = s_order + b * NPT;

    int i0 = s_start[b * 12 + k], i1 = s_start[b * 12 + k + 1];
    float m = -FLT_MAX;
    int i = i0;
    for (; i + 4 <= i1; i += 4) {
        int n0 = so[i], n1 = so[i + 1], n2 = so[i + 2], n3 = so[i + 3];
        float a0 = pc0[(size_t)n0 * 5376], b0 = pc1[(size_t)n0 * 5376];
        float a1 = pc0[(size_t)n1 * 5376], b1 = pc1[(size_t)n1 * 5376];
        float a2 = pc0[(size_t)n2 * 5376], b2 = pc1[(size_t)n2 * 5376];
        float a3 = pc0[(size_t)n3 * 5376], b3 = pc1[(size_t)n3 * 5376];
        float v0 = a0 + b0, v1 = a1 + b1, v2 = a2 + b2, v3 = a3 + b3;
        m = fmaxf(m, fmaxf(fmaxf(v0, v1), fmaxf(v2, v3)));
    }
    for (; i < i1; i++) {
        int n = so[i];
        m = fmaxf(m, pc0[(size_t)n * 5376] + pc1[(size_t)n * 5376]);
    }
    if (i0 == i1) m = 0.f;

    int HW, hw, oOff;
    if (q < 4096)      { HW = 4096; hw = q;        oOff = 0; }
    else if (q < 5120) { HW = 1024; hw = q - 4096; oOff = 2179072; }
    else               { HW = 256;  hw = q - 5120; oOff = 2723840; }

    out[oOff + (size_t)(b * (CCH + KCLS) + CCH + k) * HW + hw] = m;
}

// ---------------------------------------------------------------------------
extern "C" void kernel_launch(void* const* d_in, const int* in_sizes, int n_in,
                              void* d_out, int out_size) {
    (void)in_sizes; (void)n_in; (void)out_size;
    const float* x0      = (const float*)d_in[0];
    const float* x1      = (const float*)d_in[1];
    const float* x2      = (const float*)d_in[2];
    const float* centers = (const float*)d_in[3];
    const int*   idx     = (const int*)d_in[4];
    const int*   labels  = (const int*)d_in[5];
    float* out = (float*)d_out;

    k_tmpl_part<<<448, 256>>>(x0, x1, x2, centers, idx, labels);
    k_tmpl_reduce<<<384, 256>>>(labels);
    k_cor<<<672, 128>>>(x0, x1, x2, out);
    k_fin<<<420, 256>>>(out);
}